// round 1
// baseline (speedup 1.0000x reference)
#include <cuda_runtime.h>

#define NPTS 80000
#define NBH  32
#define KPN  15
#define CIN  128
#define D2   64
#define COUT 256
#define FKDIM (KPN*D2)   /* 960 */
#define INV_INFL 2.5f    /* 1/0.4 */
#define EPSBN 1e-5f
#define SLOPE 0.2f

/* ---------------- scratch (device globals; no allocation allowed) -------- */
__device__ float g_x1[(size_t)NPTS*D2];        /* pre-BN unary1 output */
__device__ float g_sc[(size_t)NPTS*COUT];      /* pre-BN shortcut */
__device__ float g_fk[(size_t)NPTS*FKDIM];     /* per-point kernel features */
__device__ float g_xmid[(size_t)NPTS*D2];      /* KPConv output */

__device__ float g_sum1[D2],  g_sq1[D2],  g_scale1[D2],  g_shift1[D2];
__device__ float g_sumsc[COUT],g_sqsc[COUT],g_scalesc[COUT],g_shiftsc[COUT];
__device__ float g_sum2[COUT], g_sq2[COUT], g_scale2[COUT], g_shift2[COUT];

__device__ __forceinline__ float fsqrt_approx(float x) {
    float r; asm("sqrt.approx.f32 %0, %1;" : "=f"(r) : "f"(x)); return r;
}

/* ---------------- zero stats -------------------------------------------- */
__global__ void k_zero() {
    int t = threadIdx.x;
    if (t < D2) { g_sum1[t] = 0.f; g_sq1[t] = 0.f; }
    g_sumsc[t] = 0.f; g_sqsc[t] = 0.f;
    g_sum2[t]  = 0.f; g_sq2[t]  = 0.f;
}

/* ---------------- generic 128x64 tiled fp32 GEMM ------------------------ */
/* BM=128, BN=64, BK=16, 256 threads, 8x4 micro-tile. M%128==0, N%64==0,
   K%16==0 hold for every call site. */
__device__ __forceinline__ void gemm_body(const float* __restrict__ A, int lda,
                                          const float* __restrict__ B, int ldb,
                                          float* __restrict__ C, int ldc, int Kdim)
{
    __shared__ float As[16][132];
    __shared__ float Bs[16][64];
    const int t   = threadIdx.x;
    const int m0  = blockIdx.x * 128;
    const int bn0 = blockIdx.y * 64;
    const int tx  = t & 15, ty = t >> 4;
    const int ar  = t >> 1, ac = (t & 1) * 8;
    const int br  = t >> 4, bc = (t & 15) * 4;

    float acc[8][4];
#pragma unroll
    for (int i = 0; i < 8; i++)
#pragma unroll
        for (int j = 0; j < 4; j++) acc[i][j] = 0.f;

    for (int kb = 0; kb < Kdim; kb += 16) {
        float4 a0 = *(const float4*)(A + (size_t)(m0 + ar) * lda + kb + ac);
        float4 a1 = *(const float4*)(A + (size_t)(m0 + ar) * lda + kb + ac + 4);
        float4 b0 = *(const float4*)(B + (size_t)(kb + br) * ldb + bn0 + bc);
        __syncthreads();
        As[ac+0][ar] = a0.x; As[ac+1][ar] = a0.y; As[ac+2][ar] = a0.z; As[ac+3][ar] = a0.w;
        As[ac+4][ar] = a1.x; As[ac+5][ar] = a1.y; As[ac+6][ar] = a1.z; As[ac+7][ar] = a1.w;
        *(float4*)&Bs[br][bc] = b0;
        __syncthreads();
#pragma unroll
        for (int kk = 0; kk < 16; kk++) {
            float a_[8], b_[4];
#pragma unroll
            for (int i = 0; i < 8; i++) a_[i] = As[kk][ty * 8 + i];
#pragma unroll
            for (int j = 0; j < 4; j++) b_[j] = Bs[kk][tx * 4 + j];
#pragma unroll
            for (int i = 0; i < 8; i++)
#pragma unroll
                for (int j = 0; j < 4; j++) acc[i][j] += a_[i] * b_[j];
        }
    }
#pragma unroll
    for (int i = 0; i < 8; i++) {
        float4 v = make_float4(acc[i][0], acc[i][1], acc[i][2], acc[i][3]);
        *(float4*)(C + (size_t)(m0 + ty * 8 + i) * ldc + bn0 + tx * 4) = v;
    }
}

__global__ __launch_bounds__(256) void k_gemm1(const float* A, const float* B) {
    gemm_body(A, CIN, B, D2, g_x1, D2, CIN);
}
__global__ __launch_bounds__(256) void k_gemmsc(const float* A, const float* B) {
    gemm_body(A, CIN, B, COUT, g_sc, COUT, CIN);
}
__global__ __launch_bounds__(256) void k_gemmfk(const float* B) {
    gemm_body(g_fk, FKDIM, B, D2, g_xmid, D2, FKDIM);
}
__global__ __launch_bounds__(256) void k_gemm2(const float* B, float* C) {
    gemm_body(g_xmid, D2, B, COUT, C, COUT, D2);
}

/* ---------------- channel stats (sum / sumsq over N) -------------------- */
template <int C>
__device__ __forceinline__ void stats_body(const float* __restrict__ X,
                                           float* sum, float* sq)
{
    constexpr int REPS = 256 / C;
    const int t = threadIdx.x;
    const int c = t % C;
    const int rep = t / C;
    float s = 0.f, s2 = 0.f;
    for (int r = blockIdx.x * REPS + rep; r < NPTS; r += gridDim.x * REPS) {
        float v = X[(size_t)r * C + c];
        s += v; s2 += v * v;
    }
    atomicAdd(&sum[c], s);
    atomicAdd(&sq[c], s2);
}

__global__ void k_stats1()               { stats_body<D2>(g_x1, g_sum1, g_sq1); }
__global__ void k_statssc()              { stats_body<COUT>(g_sc, g_sumsc, g_sqsc); }
__global__ void k_stats2(const float* X) { stats_body<COUT>(X, g_sum2, g_sq2); }

/* ---------------- finalize BN affine ------------------------------------ */
__device__ __forceinline__ void fin_body(const float* sum, const float* sq,
                                         const float* g, const float* b,
                                         float* scale, float* shift)
{
    int c = threadIdx.x;
    float m = sum[c] * (1.0f / NPTS);
    float v = sq[c] * (1.0f / NPTS) - m * m;
    float s = g[c] * rsqrtf(v + EPSBN);
    scale[c] = s;
    shift[c] = b[c] - m * s;
}
__global__ void k_fin1(const float* g, const float* b)  { fin_body(g_sum1, g_sq1, g, b, g_scale1, g_shift1); }
__global__ void k_finsc(const float* g, const float* b) { fin_body(g_sumsc, g_sqsc, g, b, g_scalesc, g_shiftsc); }
__global__ void k_fin2(const float* g, const float* b)  { fin_body(g_sum2, g_sq2, g, b, g_scale2, g_shift2); }

/* ---------------- KPConv: gather + influence + fk accumulation ---------- */
/* 256 threads = 8 warps = 8 points/block; lane = neighbor h; after influence
   computation the lane owns 2 feature channels (d = 2*lane, 2*lane+1). */
__global__ __launch_bounds__(256) void k_kpconv(const float* __restrict__ xyz,
                                                const int* __restrict__ nidx,
                                                const float* __restrict__ kp)
{
    __shared__ float kps[KPN][3];
    __shared__ float ws[8][NBH][KPN];   /* 15360 B */
    const int t = threadIdx.x;
    if (t < KPN * 3) ((float*)kps)[t] = kp[t];
    __syncthreads();

    const int warp = t >> 5, lane = t & 31;
    const int n = blockIdx.x * 8 + warp;

    const float cx = xyz[n * 3 + 0], cy = xyz[n * 3 + 1], cz = xyz[n * 3 + 2];
    const int j = nidx[n * NBH + lane];
    const float rx = xyz[j * 3 + 0] - cx;
    const float ry = xyz[j * 3 + 1] - cy;
    const float rz = xyz[j * 3 + 2] - cz;

#pragma unroll
    for (int k = 0; k < KPN; k++) {
        float dx = rx - kps[k][0], dy = ry - kps[k][1], dz = rz - kps[k][2];
        float sq = dx * dx + dy * dy + dz * dz;
        float w = 1.0f - fsqrt_approx(sq) * INV_INFL;
        ws[warp][lane][k] = w > 0.f ? w : 0.f;
    }
    __syncwarp();

    /* accumulation: lane owns channels 2*lane, 2*lane+1 */
    const float sc0 = g_scale1[2 * lane],     sc1 = g_scale1[2 * lane + 1];
    const float sh0 = g_shift1[2 * lane],     sh1 = g_shift1[2 * lane + 1];
    float fk0[KPN], fk1[KPN];
#pragma unroll
    for (int k = 0; k < KPN; k++) { fk0[k] = 0.f; fk1[k] = 0.f; }

    const float2* x1v = (const float2*)g_x1;
#pragma unroll 4
    for (int h = 0; h < NBH; h++) {
        int jj = __shfl_sync(0xffffffffu, j, h);
        float2 v = x1v[(size_t)jj * 32 + lane];
        float a = v.x * sc0 + sh0; a = a > 0.f ? a : SLOPE * a;
        float b = v.y * sc1 + sh1; b = b > 0.f ? b : SLOPE * b;
#pragma unroll
        for (int k = 0; k < KPN; k++) {
            float w = ws[warp][h][k];
            fk0[k] += w * a;
            fk1[k] += w * b;
        }
    }

    float2* out = (float2*)(g_fk + (size_t)n * FKDIM);
#pragma unroll
    for (int k = 0; k < KPN; k++)
        out[k * 32 + lane] = make_float2(fk0[k], fk1[k]);
}

/* ---------------- epilogue: act(bn2(x2)) + bn_sc(sc), in-place on d_out -- */
__global__ __launch_bounds__(256) void k_epilogue(float* __restrict__ out)
{
    __shared__ float s2[COUT], h2[COUT], ss[COUT], hs[COUT];
    const int t = threadIdx.x;
    s2[t] = g_scale2[t];  h2[t] = g_shift2[t];
    ss[t] = g_scalesc[t]; hs[t] = g_shiftsc[t];
    __syncthreads();

    const int idx = blockIdx.x * 256 + t;             /* float4 index */
    const int total = NPTS * (COUT / 4);
    if (idx >= total) return;
    const int c4 = (idx & 63) * 4;                    /* COUT/4 == 64 */

    float4 x = ((float4*)out)[idx];
    float4 s = ((const float4*)g_sc)[idx];
    float v0 = x.x * s2[c4 + 0] + h2[c4 + 0]; v0 = v0 > 0.f ? v0 : SLOPE * v0;
    float v1 = x.y * s2[c4 + 1] + h2[c4 + 1]; v1 = v1 > 0.f ? v1 : SLOPE * v1;
    float v2 = x.z * s2[c4 + 2] + h2[c4 + 2]; v2 = v2 > 0.f ? v2 : SLOPE * v2;
    float v3 = x.w * s2[c4 + 3] + h2[c4 + 3]; v3 = v3 > 0.f ? v3 : SLOPE * v3;
    float4 r;
    r.x = v0 + s.x * ss[c4 + 0] + hs[c4 + 0];
    r.y = v1 + s.y * ss[c4 + 1] + hs[c4 + 1];
    r.z = v2 + s.z * ss[c4 + 2] + hs[c4 + 2];
    r.w = v3 + s.w * ss[c4 + 3] + hs[c4 + 3];
    ((float4*)out)[idx] = r;
}

/* ---------------- launch ------------------------------------------------ */
extern "C" void kernel_launch(void* const* d_in, const int* in_sizes, int n_in,
                              void* d_out, int out_size)
{
    const float* feats = (const float*)d_in[0];
    const float* xyz   = (const float*)d_in[1];
    /* d_in[2] = batch (unused, all zeros) */
    const int*   nidx  = (const int*)d_in[3];
    const float* W1    = (const float*)d_in[4];
    const float* g1    = (const float*)d_in[5];
    const float* b1    = (const float*)d_in[6];
    const float* kp    = (const float*)d_in[7];
    const float* kpw   = (const float*)d_in[8];
    const float* W2    = (const float*)d_in[9];
    const float* g2    = (const float*)d_in[10];
    const float* b2    = (const float*)d_in[11];
    const float* Wsc   = (const float*)d_in[12];
    const float* gsc   = (const float*)d_in[13];
    const float* bsc   = (const float*)d_in[14];
    float* out = (float*)d_out;

    k_zero<<<1, 256>>>();

    k_gemm1 <<<dim3(NPTS / 128, 1), 256>>>(feats, W1);
    k_gemmsc<<<dim3(NPTS / 128, 4), 256>>>(feats, Wsc);

    k_stats1 <<<512, 256>>>();
    k_statssc<<<512, 256>>>();
    k_fin1 <<<1, D2>>>(g1, b1);
    k_finsc<<<1, COUT>>>(gsc, bsc);

    k_kpconv<<<NPTS / 8, 256>>>(xyz, nidx, kp);

    k_gemmfk<<<dim3(NPTS / 128, 1), 256>>>(kpw);
    k_gemm2 <<<dim3(NPTS / 128, 4), 256>>>(W2, out);

    k_stats2<<<512, 256>>>(out);
    k_fin2<<<1, COUT>>>(g2, b2);

    k_epilogue<<<(NPTS * (COUT / 4)) / 256, 256>>>(out);
}